// round 14
// baseline (speedup 1.0000x reference)
#include <cuda_runtime.h>
#include <cuda_fp16.h>
#include <stdint.h>
#include <math.h>

#define BB 64
#define SS 4096
#define EE 50
#define TT 20
#define BBTT (BB * TT)

#define CS 128
#define HALO 5
#define RR 138              // positions p = 0..137, s = s0 - 5 + p
#define NCHUNK 32

#define XT(row, col) (((((row) >> 3) * 8 + ((col) >> 3)) << 7) + (((row) & 7) << 4) + (((col) & 7) << 1))

// smem layout (bytes)
#define SM_A   0                        // 3 * 64 * 72 * 2 = 27648
#define SM_X   27648                    // 19 * 8 * 128    = 19456
#define SM_OW  (SM_X + 19456)           // 47104
#define SM_OB  (SM_OW + 4000)           // 51104
#define SM_CB  (SM_OB + 80)             // 51184
#define SM_TRASH (SM_CB + 256)          // 51440 (16B aligned)
#define SMEM_TOTAL (SM_TRASH + 64)

#define NCRF 64                         // ONE block per batch: warps 0/1/2 = fw/bw/num
#define NAH (3 * 64 * 72)               // pre-staged A halves

__device__ float g_em[(size_t)SS * BB * TT];
__device__ float g_ee[(size_t)(SS + 40) * BB * TT];
__device__ float g_num[BB];
__device__ float g_fvec[BB][TT];
__device__ float g_bvec[BB][TT];
__device__ float g_fL[BB];
__device__ float g_bL[BB];
__device__ int   g_flag[BB * NCHUNK];   // [b][chunk]
__device__ __align__(16) __half g_Ah[NAH];  // pre-staged A_kk[o][i] in half

__device__ __forceinline__ uint32_t smem_u32(const void* p) {
    uint32_t a;
    asm("{ .reg .u64 t; cvta.to.shared.u64 t, %1; cvt.u32.u64 %0, t; }" : "=r"(a) : "l"(p));
    return a;
}
__device__ __forceinline__ void ldsm_x4(uint32_t a, uint32_t r[4]) {
    asm volatile("ldmatrix.sync.aligned.m8n8.x4.shared.b16 {%0,%1,%2,%3}, [%4];"
                 : "=r"(r[0]), "=r"(r[1]), "=r"(r[2]), "=r"(r[3]) : "r"(a));
}
__device__ __forceinline__ void stsm_x2_t(uint32_t a, uint32_t r0, uint32_t r1) {
    asm volatile("stmatrix.sync.aligned.m8n8.x2.trans.shared.b16 [%0], {%1,%2};"
                 :: "r"(a), "r"(r0), "r"(r1) : "memory");
}
__device__ __forceinline__ void mma16816(float d[4], const uint32_t a[4], const uint32_t b[2]) {
    asm volatile("mma.sync.aligned.m16n8k16.row.col.f32.f16.f16.f32 "
                 "{%0,%1,%2,%3}, {%4,%5,%6,%7}, {%8,%9}, {%0,%1,%2,%3};"
                 : "+f"(d[0]), "+f"(d[1]), "+f"(d[2]), "+f"(d[3])
                 : "r"(a[0]), "r"(a[1]), "r"(a[2]), "r"(a[3]), "r"(b[0]), "r"(b[1]));
}
__device__ __forceinline__ uint32_t h2u(__half2 h) {
    return *reinterpret_cast<uint32_t*>(&h);
}
__device__ __forceinline__ void wait_flag(int b, int c) {
    volatile int* f = &g_flag[b * NCHUNK + c];
    while (*f == 0) __nanosleep(100);
    __threadfence();
}

// ---------------------------------------------------------------------------
// Prep: zero flags + pre-stage A (transpose + half-convert, incl. zero pad)
// ---------------------------------------------------------------------------
__global__ void prep_kernel(const float* __restrict__ conv_w)
{
    int idx = blockIdx.x * blockDim.x + threadIdx.x;
    if (idx < BB * NCHUNK) g_flag[idx] = 0;
    if (idx < NAH) {
        int kk = idx / (64 * 72);
        int rem = idx - kk * (64 * 72);
        int o = rem / 72, i = rem - o * 72;
        float v = (o < EE && i < EE) ? conv_w[o * 150 + i * 3 + kk] : 0.0f;
        g_Ah[idx] = __float2half(v);
    }
}

// ===========================================================================
// CRF helpers
// ===========================================================================
__device__ __forceinline__ float crf_dot(float c, const float* E)
{
    float a0 = 0.f, a1 = 0.f, a2 = 0.f, a3 = 0.f;
    #pragma unroll
    for (int i = 0; i < TT; i += 4) {
        a0 = fmaf(__shfl_sync(0xffffffffu, c, i + 0), E[i + 0], a0);
        a1 = fmaf(__shfl_sync(0xffffffffu, c, i + 1), E[i + 1], a1);
        a2 = fmaf(__shfl_sync(0xffffffffu, c, i + 2), E[i + 2], a2);
        a3 = fmaf(__shfl_sync(0xffffffffu, c, i + 3), E[i + 3], a3);
    }
    return (a0 + a1) + (a2 + a3);
}

#define RENORM() do { \
    val *= rinv; L += lg; \
    float _m = __shfl_sync(0xffffffffu, val, 0); \
    rinv = __frcp_rn(_m); lg = __log2f(_m); \
} while (0)

// ===========================================================================
// Fused kernel: bid < NCRF -> CRF block (warps 0/1/2 = fw/bw/num of batch bid)
//               else          conv block. 3 blocks/SM (<=84 regs).
// ===========================================================================
__global__ __launch_bounds__(256, 3)
void fused_kernel(const int* __restrict__ token_id,
                  const int* __restrict__ tag,
                  const float* __restrict__ embed_table,
                  const float* __restrict__ conv_b,
                  const float* __restrict__ out_w,
                  const float* __restrict__ out_b,
                  const float* __restrict__ start_trans,
                  const float* __restrict__ end_trans,
                  const float* __restrict__ trans)
{
    const int bid = blockIdx.x;
    const int tid = threadIdx.x;

    if (bid < NCRF) {
        // ================= CRF path: 3 live warps per block =================
        if (tid >= 96) return;
        const int dir = tid >> 5;          // warp 0 fw, 1 bw, 2 numerator
        const int b   = bid;
        const int j   = tid & 31;
        const bool ok = (j < TT);
        const int jj  = ok ? j : 0;

        if (dir == 2) {
            float sum = 0.0f;
            for (int ci = 0; ci < NCHUNK; ++ci) {
                int c = (ci & 1) ? (NCHUNK - 1 - (ci >> 1)) : (ci >> 1);
                wait_flag(b, c);
                for (int q = j; q < CS; q += 32) {
                    int s = c * CS + q;
                    int tg = tag[b * SS + s];
                    sum += g_em[(s * BB + b) * TT + tg];
                    if (s > 0)      sum += trans[tag[b * SS + s - 1] * TT + tg];
                    if (s == 0)     sum += start_trans[tg];
                    if (s == SS-1)  sum += end_trans[tg];
                }
            }
            #pragma unroll
            for (int o = 16; o > 0; o >>= 1) sum += __shfl_xor_sync(0xffffffffu, sum, o);
            if (j == 0) g_num[b] = sum;
            return;
        }

        float E[TT];
        float val, L = 0.0f, rinv = 1.0f, lg = 0.0f;
        float ea[8], eb[8];
        const float* base = g_ee + b * TT + jj;

        if (dir == 0) {
            // ---- forward: steps t=1..2047 (chunks 0..15) ----
            #pragma unroll
            for (int i = 0; i < TT; ++i) E[i] = ok ? __expf(trans[i * TT + jj]) : 0.0f;
            wait_flag(b, 0);
            val = ok ? __expf(start_trans[jj]) * base[0] : 0.0f;
            {   // peel t=1..7
                float ep[7];
                #pragma unroll
                for (int k = 0; k < 7; ++k) ep[k] = base[(1 + k) * BBTT];
                #pragma unroll
                for (int k = 0; k < 7; ++k) val = ep[k] * crf_dot(val, E);
                RENORM();
            }
            // t=8..127: 15 groups
            #pragma unroll
            for (int k = 0; k < 8; ++k) ea[k] = base[(8 + k) * BBTT];
            #pragma unroll 1
            for (int g = 0; g < 15; ++g) {
                if (g < 14) {
                    int t1 = 16 + g * 8;
                    #pragma unroll
                    for (int k = 0; k < 8; ++k) eb[k] = base[(t1 + k) * BBTT];
                }
                #pragma unroll
                for (int k = 0; k < 8; ++k) val = ea[k] * crf_dot(val, E);
                RENORM();
                #pragma unroll
                for (int k = 0; k < 8; ++k) ea[k] = eb[k];
            }
            // chunks 1..15: 16 groups each
            #pragma unroll 1
            for (int c = 1; c < 16; ++c) {
                wait_flag(b, c);
                int tb = c * CS;
                #pragma unroll
                for (int k = 0; k < 8; ++k) ea[k] = base[(tb + k) * BBTT];
                #pragma unroll 1
                for (int g = 0; g < 16; ++g) {
                    if (g < 15) {
                        int t1 = tb + 8 + g * 8;
                        #pragma unroll
                        for (int k = 0; k < 8; ++k) eb[k] = base[(t1 + k) * BBTT];
                    }
                    #pragma unroll
                    for (int k = 0; k < 8; ++k) val = ea[k] * crf_dot(val, E);
                    RENORM();
                    #pragma unroll
                    for (int k = 0; k < 8; ++k) ea[k] = eb[k];
                }
            }
            val *= rinv; L += lg;
            if (ok) g_fvec[b][jj] = val;
            if (j == 0) g_fL[b] = L;
        } else {
            // ---- backward: 2048 steps consuming e_4095..e_2048 (chunks 31..16) ----
            #pragma unroll
            for (int i = 0; i < TT; ++i) E[i] = ok ? __expf(trans[jj * TT + i]) : 0.0f;
            val = ok ? __expf(end_trans[jj]) : 0.0f;
            #pragma unroll 1
            for (int c = NCHUNK - 1; c >= 16; --c) {
                wait_flag(b, c);
                int tt0 = c * CS + 127;
                #pragma unroll
                for (int k = 0; k < 8; ++k) ea[k] = base[(tt0 - k) * BBTT];
                #pragma unroll 1
                for (int g = 0; g < 16; ++g) {
                    if (g < 15) {
                        int t1 = tt0 - 8 - g * 8;
                        #pragma unroll
                        for (int k = 0; k < 8; ++k) eb[k] = base[(t1 - k) * BBTT];
                    }
                    #pragma unroll
                    for (int k = 0; k < 8; ++k) val = crf_dot(ea[k] * val, E);
                    RENORM();
                    #pragma unroll
                    for (int k = 0; k < 8; ++k) ea[k] = eb[k];
                }
            }
            val *= rinv; L += lg;
            if (ok) g_bvec[b][jj] = val;
            if (j == 0) g_bL[b] = L;
        }
        return;
    }

    // ================= Conv path =================
    extern __shared__ char smem[];
    float*  ow = (float*)(smem + SM_OW);
    float*  ob = (float*)(smem + SM_OB);
    float*  cb = (float*)(smem + SM_CB);

    const int cv = bid - NCRF;
    const int by = cv & 63;
    const int ci = cv >> 6;                 // 0..31
    const int chunk = (ci & 1) ? (NCHUNK - 1 - (ci >> 1)) : (ci >> 1);
    const int s0 = chunk * CS;

    // copy pre-staged A (27648 B, uint4) + zero X region only
    {
        const uint4* gA = (const uint4*)g_Ah;
        uint4* sA = (uint4*)(smem + SM_A);
        for (int i = tid; i < 27648 / 16; i += 256) sA[i] = gA[i];
        uint32_t* xz = (uint32_t*)(smem + SM_X);
        for (int i = tid; i < 19456 / 4; i += 256) xz[i] = 0u;
    }
    for (int i = tid; i < 1000; i += 256) ow[i] = out_w[i];
    if (tid < TT) ob[tid] = out_b[tid];
    if (tid < 64) cb[tid] = (tid < EE) ? conv_b[tid] : 0.0f;
    __syncthreads();

    for (int idx = tid; idx < RR * EE; idx += 256) {
        int p = idx / EE, e = idx - p * EE;
        int s = s0 - HALO + p;
        if (s >= 0 && s < SS) {
            int tok = token_id[by * SS + s];
            *(__half*)(smem + SM_X + XT(p + 1, e)) = __float2half(embed_table[tok * EE + e]);
        }
    }
    __syncthreads();

    const int lane = tid & 31, w = tid >> 5;
    const int m0 = (w & 3) * 16;
    const int n0base = (w >> 2) * 72;

    const uint32_t su = smem_u32(smem);
    const uint32_t XBu = su + SM_X;
    const uint32_t trash_u = su + SM_TRASH;

    // A fragment address (per thread, lane-constant within (kk,ks)):
    // addr = Au + kk*9216 + arow*144 + ks*32 + acolh*2
    const uint32_t aoff = (su + SM_A) + (m0 + (lane & 15)) * 144 + (8 * (lane >> 4)) * 2;

    const int pad_lo = (s0 == 0) ? HALO : 0;
    int seq_hi = SS - s0 + HALO; if (seq_hi > RR) seq_hi = RR;
    const int gid = lane >> 2, tig = lane & 3;
    const int o0 = m0 + gid, o1 = o0 + 8;
    const float cb0 = cb[o0], cb1 = cb[o1];
    const int lane7 = lane & 7;
    const int g8    = lane >> 3;

    uint32_t bbase[3];
    #pragma unroll
    for (int kk = 0; kk < 3; ++kk) {
        int row_l = n0base + lane7 + kk;
        bbase[kk] = XBu + (row_l >> 3) * 1024 + (row_l & 7) * 16 + g8 * 128;
    }
    const int strow = n0base + lane7 + 1;
    const uint32_t stbase = XBu + (strow >> 3) * 1024 + (strow & 7) * 16
                               + (2 * (w & 3) + ((lane >> 3) & 1)) * 128;
    const int pr0 = n0base + lane7;

    __half2 xh[9][2];
    #pragma unroll
    for (int nt = 0; nt < 9; ++nt) {
        int pA = n0base + nt * 8 + 2 * tig;
        xh[nt][0] = __halves2half2(*(__half*)(smem + SM_X + XT(pA + 1, o0)),
                                   *(__half*)(smem + SM_X + XT(pA + 2, o0)));
        xh[nt][1] = __halves2half2(*(__half*)(smem + SM_X + XT(pA + 1, o1)),
                                   *(__half*)(smem + SM_X + XT(pA + 2, o1)));
    }

    #pragma unroll 1
    for (int l = 1; l <= 5; ++l) {
        float acc[9][4];
        #pragma unroll
        for (int nt = 0; nt < 9; ++nt)
            #pragma unroll
            for (int r = 0; r < 4; ++r) acc[nt][r] = 0.0f;

        #pragma unroll
        for (int kk = 0; kk < 3; ++kk)
            #pragma unroll
            for (int ksp = 0; ksp < 2; ++ksp) {
                uint32_t afa[4], afb[4];
                ldsm_x4(aoff + kk * 9216 + (2 * ksp)     * 32, afa);
                ldsm_x4(aoff + kk * 9216 + (2 * ksp + 1) * 32, afb);
                uint32_t base = bbase[kk] + ksp * 512;
                #pragma unroll
                for (int nt = 0; nt < 9; ++nt) {
                    uint32_t bf[4];
                    ldsm_x4(base + nt * 1024, bf);
                    mma16816(acc[nt], afa, bf);
                    mma16816(acc[nt], afb, bf + 2);
                }
            }

        // swish + residual in registers
        #pragma unroll
        for (int nt = 0; nt < 9; ++nt) {
            float y0 = acc[nt][0] + cb0, y1 = acc[nt][1] + cb0;
            float y2 = acc[nt][2] + cb1, y3 = acc[nt][3] + cb1;
            float nx0 = __low2float(xh[nt][0])  + __fdividef(y0, 1.f + __expf(-y0));
            float nx1 = __high2float(xh[nt][0]) + __fdividef(y1, 1.f + __expf(-y1));
            float nx2 = __low2float(xh[nt][1])  + __fdividef(y2, 1.f + __expf(-y2));
            float nx3 = __high2float(xh[nt][1]) + __fdividef(y3, 1.f + __expf(-y3));
            xh[nt][0] = __floats2half2_rn(nx0, nx1);
            xh[nt][1] = __floats2half2_rn(nx2, nx3);
        }
        __syncthreads();   // ldmatrix reads done before X overwritten

        #pragma unroll
        for (int nt = 0; nt < 9; ++nt) {
            int pr = pr0 + 8 * nt;
            uint32_t addr = (pr >= pad_lo && pr < seq_hi) ? (stbase + nt * 1024) : trash_u;
            stsm_x2_t(addr, h2u(xh[nt][0]), h2u(xh[nt][1]));
        }
        __syncthreads();   // X updated before next layer / emissions
    }

    // emissions
    for (int idx = tid; idx < TT * CS; idx += 256) {
        int t = idx % TT;
        int q = idx / TT;
        int s = s0 + q;
        int row = q + HALO + 1;
        const char* rbase = smem + SM_X + (row >> 3) * 1024 + (row & 7) * 16;
        float acc = ob[t];
        const float* owt = &ow[t * EE];
        #pragma unroll
        for (int c = 0; c < 6; ++c) {
            uint4 v = *(const uint4*)(rbase + c * 128);
            const __half2* hp = (const __half2*)&v;
            #pragma unroll
            for (int m = 0; m < 4; ++m) {
                acc = fmaf(__low2float(hp[m]),  owt[c * 8 + 2 * m],     acc);
                acc = fmaf(__high2float(hp[m]), owt[c * 8 + 2 * m + 1], acc);
            }
        }
        {
            uint32_t v = *(const uint32_t*)(rbase + 6 * 128);
            __half2 h = *(const __half2*)&v;
            acc = fmaf(__low2float(h),  owt[48], acc);
            acc = fmaf(__high2float(h), owt[49], acc);
        }
        int gi = (s * BB + by) * TT + t;
        g_em[gi] = acc;
        g_ee[gi] = __expf(acc);
    }

    // publish chunk: release fence, then flag
    __threadfence();
    __syncthreads();
    if (tid == 0) *(volatile int*)&g_flag[by * NCHUNK + chunk] = 1;
}

// ===========================================================================
// Final: den = ln2*(Lf+Lb) + log(dot(fvec,bvec)); out = sum(den - num)
// ===========================================================================
__global__ void final_kernel(float* __restrict__ out)
{
    __shared__ float red[64];
    int t = threadIdx.x;
    float s = 0.0f;
    #pragma unroll
    for (int i = 0; i < TT; ++i) s += g_fvec[t][i] * g_bvec[t][i];
    float den = (g_fL[t] + g_bL[t]) * 0.69314718055994531f + logf(s);
    red[t] = den - g_num[t];
    __syncthreads();
    for (int k = 32; k > 0; k >>= 1) {
        if (t < k) red[t] += red[t + k];
        __syncthreads();
    }
    if (t == 0) out[0] = red[0];
}

extern "C" void kernel_launch(void* const* d_in, const int* in_sizes, int n_in,
                              void* d_out, int out_size)
{
    const int*   token_id    = (const int*)d_in[0];
    const int*   tag_id      = (const int*)d_in[1];
    const float* embed_table = (const float*)d_in[2];
    const float* conv_w      = (const float*)d_in[3];
    const float* conv_b      = (const float*)d_in[4];
    const float* out_w       = (const float*)d_in[5];
    const float* out_b       = (const float*)d_in[6];
    const float* start_trans = (const float*)d_in[7];
    const float* end_trans   = (const float*)d_in[8];
    const float* trans       = (const float*)d_in[9];

    cudaFuncSetAttribute(fused_kernel,
                         cudaFuncAttributeMaxDynamicSharedMemorySize, SMEM_TOTAL);

    prep_kernel<<<54, 256>>>(conv_w);
    fused_kernel<<<NCRF + (SS / CS) * BB, 256, SMEM_TOTAL>>>(
        token_id, tag_id, embed_table, conv_b, out_w, out_b,
        start_trans, end_trans, trans);
    final_kernel<<<1, 64>>>((float*)d_out);
}

// round 17
// speedup vs baseline: 1.0693x; 1.0693x over previous
#include <cuda_runtime.h>
#include <cuda_fp16.h>
#include <stdint.h>
#include <math.h>

#define BB 64
#define SS 4096
#define EE 50
#define TT 20
#define BBTT (BB * TT)

#define CS 128
#define HALO 5
#define RR 138              // positions p = 0..137, s = s0 - 5 + p
#define NCHUNK 32

#define XT(row, col) (((((row) >> 3) * 8 + ((col) >> 3)) << 7) + (((row) & 7) << 4) + (((col) & 7) << 1))

// smem layout (bytes)
#define SM_A   0                        // 3 * 64 * 72 * 2 = 27648
#define SM_X   27648                    // 19 * 8 * 128    = 19456
#define SM_OW  (SM_X + 19456)           // 47104
#define SM_OB  (SM_OW + 4000)           // 51104
#define SM_CB  (SM_OB + 80)             // 51184
#define SM_TRASH (SM_CB + 256)          // 51440 (16B aligned)
#define SMEM_TOTAL (SM_TRASH + 64)

#define NCRF 64                         // ONE block per batch: warps 0/1/2 = fw/bw/num
#define NAH (3 * 64 * 72)               // pre-staged A halves

__device__ float g_em[(size_t)SS * BB * TT];
__device__ float g_ee[(size_t)(SS + 40) * BB * TT];
__device__ float g_num[BB];
__device__ float g_fvec[BB][TT];
__device__ float g_bvec[BB][TT];
__device__ float g_fL[BB];
__device__ float g_bL[BB];
__device__ int   g_flag[BB * NCHUNK];   // [b][chunk]
__device__ __align__(16) __half g_Ah[NAH];  // pre-staged A_kk[o][i] in half

__device__ __forceinline__ uint32_t smem_u32(const void* p) {
    uint32_t a;
    asm("{ .reg .u64 t; cvta.to.shared.u64 t, %1; cvt.u32.u64 %0, t; }" : "=r"(a) : "l"(p));
    return a;
}
__device__ __forceinline__ void ldsm_x4(uint32_t a, uint32_t r[4]) {
    asm volatile("ldmatrix.sync.aligned.m8n8.x4.shared.b16 {%0,%1,%2,%3}, [%4];"
                 : "=r"(r[0]), "=r"(r[1]), "=r"(r[2]), "=r"(r[3]) : "r"(a));
}
__device__ __forceinline__ void stsm_x2_t(uint32_t a, uint32_t r0, uint32_t r1) {
    asm volatile("stmatrix.sync.aligned.m8n8.x2.trans.shared.b16 [%0], {%1,%2};"
                 :: "r"(a), "r"(r0), "r"(r1) : "memory");
}
__device__ __forceinline__ void mma16816(float d[4], const uint32_t a[4], const uint32_t b[2]) {
    asm volatile("mma.sync.aligned.m16n8k16.row.col.f32.f16.f16.f32 "
                 "{%0,%1,%2,%3}, {%4,%5,%6,%7}, {%8,%9}, {%0,%1,%2,%3};"
                 : "+f"(d[0]), "+f"(d[1]), "+f"(d[2]), "+f"(d[3])
                 : "r"(a[0]), "r"(a[1]), "r"(a[2]), "r"(a[3]), "r"(b[0]), "r"(b[1]));
}
__device__ __forceinline__ uint32_t h2u(__half2 h) {
    return *reinterpret_cast<uint32_t*>(&h);
}
__device__ __forceinline__ void wait_flag(int b, int c) {
    volatile int* f = &g_flag[b * NCHUNK + c];
    while (*f == 0) __nanosleep(100);
    __threadfence();
}

// ---------------------------------------------------------------------------
// Prep: zero flags + pre-stage A (transpose + half-convert, incl. zero pad)
// ---------------------------------------------------------------------------
__global__ void prep_kernel(const float* __restrict__ conv_w)
{
    int idx = blockIdx.x * blockDim.x + threadIdx.x;
    if (idx < BB * NCHUNK) g_flag[idx] = 0;
    if (idx < NAH) {
        int kk = idx / (64 * 72);
        int rem = idx - kk * (64 * 72);
        int o = rem / 72, i = rem - o * 72;
        float v = (o < EE && i < EE) ? conv_w[o * 150 + i * 3 + kk] : 0.0f;
        g_Ah[idx] = __float2half(v);
    }
}

// ===========================================================================
// CRF helpers
// ===========================================================================
__device__ __forceinline__ float crf_dot(float c, const float* E)
{
    float a0 = 0.f, a1 = 0.f, a2 = 0.f, a3 = 0.f;
    #pragma unroll
    for (int i = 0; i < TT; i += 4) {
        a0 = fmaf(__shfl_sync(0xffffffffu, c, i + 0), E[i + 0], a0);
        a1 = fmaf(__shfl_sync(0xffffffffu, c, i + 1), E[i + 1], a1);
        a2 = fmaf(__shfl_sync(0xffffffffu, c, i + 2), E[i + 2], a2);
        a3 = fmaf(__shfl_sync(0xffffffffu, c, i + 3), E[i + 3], a3);
    }
    return (a0 + a1) + (a2 + a3);
}

#define RENORM() do { \
    val *= rinv; L += lg; \
    float _m = __shfl_sync(0xffffffffu, val, 0); \
    rinv = __frcp_rn(_m); lg = __log2f(_m); \
} while (0)

// ===========================================================================
// Fused kernel: bid < NCRF -> CRF block (warps 0/1/2 = fw/bw/num of batch bid)
//               else          conv block (R11 mainloop, occ 2).
// ===========================================================================
__global__ __launch_bounds__(256, 2)
void fused_kernel(const int* __restrict__ token_id,
                  const int* __restrict__ tag,
                  const float* __restrict__ embed_table,
                  const float* __restrict__ conv_b,
                  const float* __restrict__ out_w,
                  const float* __restrict__ out_b,
                  const float* __restrict__ start_trans,
                  const float* __restrict__ end_trans,
                  const float* __restrict__ trans)
{
    const int bid = blockIdx.x;
    const int tid = threadIdx.x;

    if (bid < NCRF) {
        // ================= CRF path: 3 live warps per block =================
        if (tid >= 96) return;
        const int dir = tid >> 5;          // warp 0 fw, 1 bw, 2 numerator
        const int b   = bid;
        const int j   = tid & 31;
        const bool ok = (j < TT);
        const int jj  = ok ? j : 0;

        if (dir == 2) {
            float sum = 0.0f;
            for (int ci = 0; ci < NCHUNK; ++ci) {
                int c = (ci & 1) ? (NCHUNK - 1 - (ci >> 1)) : (ci >> 1);
                wait_flag(b, c);
                for (int q = j; q < CS; q += 32) {
                    int s = c * CS + q;
                    int tg = tag[b * SS + s];
                    sum += g_em[(s * BB + b) * TT + tg];
                    if (s > 0)      sum += trans[tag[b * SS + s - 1] * TT + tg];
                    if (s == 0)     sum += start_trans[tg];
                    if (s == SS-1)  sum += end_trans[tg];
                }
            }
            #pragma unroll
            for (int o = 16; o > 0; o >>= 1) sum += __shfl_xor_sync(0xffffffffu, sum, o);
            if (j == 0) g_num[b] = sum;
            return;
        }

        float E[TT];
        float val, L = 0.0f, rinv = 1.0f, lg = 0.0f;
        float ea[8], eb[8];
        const float* base = g_ee + b * TT + jj;

        if (dir == 0) {
            // ---- forward: steps t=1..2047 (chunks 0..15) ----
            #pragma unroll
            for (int i = 0; i < TT; ++i) E[i] = ok ? __expf(trans[i * TT + jj]) : 0.0f;
            wait_flag(b, 0);
            val = ok ? __expf(start_trans[jj]) * base[0] : 0.0f;
            {   // peel t=1..7
                float ep[7];
                #pragma unroll
                for (int k = 0; k < 7; ++k) ep[k] = base[(1 + k) * BBTT];
                #pragma unroll
                for (int k = 0; k < 7; ++k) val = ep[k] * crf_dot(val, E);
                RENORM();
            }
            // t=8..127: 15 groups
            #pragma unroll
            for (int k = 0; k < 8; ++k) ea[k] = base[(8 + k) * BBTT];
            #pragma unroll 1
            for (int g = 0; g < 15; ++g) {
                if (g < 14) {
                    int t1 = 16 + g * 8;
                    #pragma unroll
                    for (int k = 0; k < 8; ++k) eb[k] = base[(t1 + k) * BBTT];
                }
                #pragma unroll
                for (int k = 0; k < 8; ++k) val = ea[k] * crf_dot(val, E);
                RENORM();
                #pragma unroll
                for (int k = 0; k < 8; ++k) ea[k] = eb[k];
            }
            // chunks 1..15: 16 groups each
            #pragma unroll 1
            for (int c = 1; c < 16; ++c) {
                wait_flag(b, c);
                int tb = c * CS;
                #pragma unroll
                for (int k = 0; k < 8; ++k) ea[k] = base[(tb + k) * BBTT];
                #pragma unroll 1
                for (int g = 0; g < 16; ++g) {
                    if (g < 15) {
                        int t1 = tb + 8 + g * 8;
                        #pragma unroll
                        for (int k = 0; k < 8; ++k) eb[k] = base[(t1 + k) * BBTT];
                    }
                    #pragma unroll
                    for (int k = 0; k < 8; ++k) val = ea[k] * crf_dot(val, E);
                    RENORM();
                    #pragma unroll
                    for (int k = 0; k < 8; ++k) ea[k] = eb[k];
                }
            }
            val *= rinv; L += lg;
            if (ok) g_fvec[b][jj] = val;
            if (j == 0) g_fL[b] = L;
        } else {
            // ---- backward: 2048 steps consuming e_4095..e_2048 (chunks 31..16) ----
            #pragma unroll
            for (int i = 0; i < TT; ++i) E[i] = ok ? __expf(trans[jj * TT + i]) : 0.0f;
            val = ok ? __expf(end_trans[jj]) : 0.0f;
            #pragma unroll 1
            for (int c = NCHUNK - 1; c >= 16; --c) {
                wait_flag(b, c);
                int tt0 = c * CS + 127;
                #pragma unroll
                for (int k = 0; k < 8; ++k) ea[k] = base[(tt0 - k) * BBTT];
                #pragma unroll 1
                for (int g = 0; g < 16; ++g) {
                    if (g < 15) {
                        int t1 = tt0 - 8 - g * 8;
                        #pragma unroll
                        for (int k = 0; k < 8; ++k) eb[k] = base[(t1 - k) * BBTT];
                    }
                    #pragma unroll
                    for (int k = 0; k < 8; ++k) val = crf_dot(ea[k] * val, E);
                    RENORM();
                    #pragma unroll
                    for (int k = 0; k < 8; ++k) ea[k] = eb[k];
                }
            }
            val *= rinv; L += lg;
            if (ok) g_bvec[b][jj] = val;
            if (j == 0) g_bL[b] = L;
        }
        return;
    }

    // ================= Conv path (R11 mainloop; prep-staged A setup) =========
    extern __shared__ char smem[];
    float*  ow = (float*)(smem + SM_OW);
    float*  ob = (float*)(smem + SM_OB);
    float*  cb = (float*)(smem + SM_CB);

    const int cv = bid - NCRF;
    const int by = cv & 63;
    const int ci = cv >> 6;                 // 0..31
    const int chunk = (ci & 1) ? (NCHUNK - 1 - (ci >> 1)) : (ci >> 1);
    const int s0 = chunk * CS;

    // copy pre-staged A (27648 B, uint4) + zero X region only
    {
        const uint4* gA = (const uint4*)g_Ah;
        uint4* sA = (uint4*)(smem + SM_A);
        for (int i = tid; i < 27648 / 16; i += 256) sA[i] = gA[i];
        uint32_t* xz = (uint32_t*)(smem + SM_X);
        for (int i = tid; i < 19456 / 4; i += 256) xz[i] = 0u;
    }
    for (int i = tid; i < 1000; i += 256) ow[i] = out_w[i];
    if (tid < TT) ob[tid] = out_b[tid];
    if (tid < 64) cb[tid] = (tid < EE) ? conv_b[tid] : 0.0f;
    __syncthreads();

    for (int idx = tid; idx < RR * EE; idx += 256) {
        int p = idx / EE, e = idx - p * EE;
        int s = s0 - HALO + p;
        if (s >= 0 && s < SS) {
            int tok = token_id[by * SS + s];
            *(__half*)(smem + SM_X + XT(p + 1, e)) = __float2half(embed_table[tok * EE + e]);
        }
    }
    __syncthreads();

    const int lane = tid & 31, w = tid >> 5;
    const int m0 = (w & 3) * 16;
    const int n0base = (w >> 2) * 72;

    const uint32_t su = smem_u32(smem);
    const uint32_t XBu = su + SM_X;
    const uint32_t trash_u = su + SM_TRASH;

    // A fragments: 3 kk x 4 ksteps, resident for all layers
    uint32_t af[12][4];
    {
        const uint32_t abase = (su + SM_A) + (m0 + (lane & 15)) * 144
                             + (8 * (lane >> 4)) * 2;
        #pragma unroll
        for (int kk = 0; kk < 3; ++kk)
            #pragma unroll
            for (int ks = 0; ks < 4; ++ks)
                ldsm_x4(abase + kk * 9216 + ks * 32, af[kk * 4 + ks]);
    }

    const int pad_lo = (s0 == 0) ? HALO : 0;
    int seq_hi = SS - s0 + HALO; if (seq_hi > RR) seq_hi = RR;
    const int gid = lane >> 2, tig = lane & 3;
    const int o0 = m0 + gid, o1 = o0 + 8;
    const float cb0 = cb[o0], cb1 = cb[o1];
    const int lane7 = lane & 7;
    const int g8    = lane >> 3;

    uint32_t bbase[3];
    #pragma unroll
    for (int kk = 0; kk < 3; ++kk) {
        int row_l = n0base + lane7 + kk;
        bbase[kk] = XBu + (row_l >> 3) * 1024 + (row_l & 7) * 16 + g8 * 128;
    }
    const int strow = n0base + lane7 + 1;
    const uint32_t stbase = XBu + (strow >> 3) * 1024 + (strow & 7) * 16
                               + (2 * (w & 3) + ((lane >> 3) & 1)) * 128;
    const int pr0 = n0base + lane7;

    __half2 xh[9][2];
    #pragma unroll
    for (int nt = 0; nt < 9; ++nt) {
        int pA = n0base + nt * 8 + 2 * tig;
        xh[nt][0] = __halves2half2(*(__half*)(smem + SM_X + XT(pA + 1, o0)),
                                   *(__half*)(smem + SM_X + XT(pA + 2, o0)));
        xh[nt][1] = __halves2half2(*(__half*)(smem + SM_X + XT(pA + 1, o1)),
                                   *(__half*)(smem + SM_X + XT(pA + 2, o1)));
    }

    #pragma unroll 1
    for (int l = 1; l <= 5; ++l) {
        #pragma unroll
        for (int nt0 = 0; nt0 < 9; nt0 += 2) {
            float acc0[4] = {0.f, 0.f, 0.f, 0.f};
            float acc1[4] = {0.f, 0.f, 0.f, 0.f};
            const bool two = (nt0 + 1 < 9);
            #pragma unroll
            for (int kk = 0; kk < 3; ++kk)
                #pragma unroll
                for (int ksp = 0; ksp < 2; ++ksp) {
                    uint32_t base = bbase[kk] + ksp * 512;
                    uint32_t bf[4];
                    ldsm_x4(base + nt0 * 1024, bf);
                    mma16816(acc0, af[kk * 4 + 2 * ksp],     bf);
                    mma16816(acc0, af[kk * 4 + 2 * ksp + 1], bf + 2);
                    if (two) {
                        uint32_t bg[4];
                        ldsm_x4(base + (nt0 + 1) * 1024, bg);
                        mma16816(acc1, af[kk * 4 + 2 * ksp],     bg);
                        mma16816(acc1, af[kk * 4 + 2 * ksp + 1], bg + 2);
                    }
                }
            {
                float y0 = acc0[0] + cb0, y1 = acc0[1] + cb0;
                float y2 = acc0[2] + cb1, y3 = acc0[3] + cb1;
                float nx0 = __low2float(xh[nt0][0])  + __fdividef(y0, 1.f + __expf(-y0));
                float nx1 = __high2float(xh[nt0][0]) + __fdividef(y1, 1.f + __expf(-y1));
                float nx2 = __low2float(xh[nt0][1])  + __fdividef(y2, 1.f + __expf(-y2));
                float nx3 = __high2float(xh[nt0][1]) + __fdividef(y3, 1.f + __expf(-y3));
                xh[nt0][0] = __floats2half2_rn(nx0, nx1);
                xh[nt0][1] = __floats2half2_rn(nx2, nx3);
            }
            if (two) {
                float y0 = acc1[0] + cb0, y1 = acc1[1] + cb0;
                float y2 = acc1[2] + cb1, y3 = acc1[3] + cb1;
                float nx0 = __low2float(xh[nt0+1][0])  + __fdividef(y0, 1.f + __expf(-y0));
                float nx1 = __high2float(xh[nt0+1][0]) + __fdividef(y1, 1.f + __expf(-y1));
                float nx2 = __low2float(xh[nt0+1][1])  + __fdividef(y2, 1.f + __expf(-y2));
                float nx3 = __high2float(xh[nt0+1][1]) + __fdividef(y3, 1.f + __expf(-y3));
                xh[nt0+1][0] = __floats2half2_rn(nx0, nx1);
                xh[nt0+1][1] = __floats2half2_rn(nx2, nx3);
            }
        }
        __syncthreads();   // ldmatrix reads done before X overwritten

        #pragma unroll
        for (int nt = 0; nt < 9; ++nt) {
            int pr = pr0 + 8 * nt;
            uint32_t addr = (pr >= pad_lo && pr < seq_hi) ? (stbase + nt * 1024) : trash_u;
            stsm_x2_t(addr, h2u(xh[nt][0]), h2u(xh[nt][1]));
        }
        __syncthreads();   // X updated before next layer / emissions
    }

    // emissions
    for (int idx = tid; idx < TT * CS; idx += 256) {
        int t = idx % TT;
        int q = idx / TT;
        int s = s0 + q;
        int row = q + HALO + 1;
        const char* rbase = smem + SM_X + (row >> 3) * 1024 + (row & 7) * 16;
        float acc = ob[t];
        const float* owt = &ow[t * EE];
        #pragma unroll
        for (int c = 0; c < 6; ++c) {
            uint4 v = *(const uint4*)(rbase + c * 128);
            const __half2* hp = (const __half2*)&v;
            #pragma unroll
            for (int m = 0; m < 4; ++m) {
                acc = fmaf(__low2float(hp[m]),  owt[c * 8 + 2 * m],     acc);
                acc = fmaf(__high2float(hp[m]), owt[c * 8 + 2 * m + 1], acc);
            }
        }
        {
            uint32_t v = *(const uint32_t*)(rbase + 6 * 128);
            __half2 h = *(const __half2*)&v;
            acc = fmaf(__low2float(h),  owt[48], acc);
            acc = fmaf(__high2float(h), owt[49], acc);
        }
        int gi = (s * BB + by) * TT + t;
        g_em[gi] = acc;
        g_ee[gi] = __expf(acc);
    }

    // publish chunk: release fence, then flag
    __threadfence();
    __syncthreads();
    if (tid == 0) *(volatile int*)&g_flag[by * NCHUNK + chunk] = 1;
}

// ===========================================================================
// Final: den = ln2*(Lf+Lb) + log(dot(fvec,bvec)); out = sum(den - num)
// ===========================================================================
__global__ void final_kernel(float* __restrict__ out)
{
    __shared__ float red[64];
    int t = threadIdx.x;
    float s = 0.0f;
    #pragma unroll
    for (int i = 0; i < TT; ++i) s += g_fvec[t][i] * g_bvec[t][i];
    float den = (g_fL[t] + g_bL[t]) * 0.69314718055994531f + logf(s);
    red[t] = den - g_num[t];
    __syncthreads();
    for (int k = 32; k > 0; k >>= 1) {
        if (t < k) red[t] += red[t + k];
        __syncthreads();
    }
    if (t == 0) out[0] = red[0];
}

extern "C" void kernel_launch(void* const* d_in, const int* in_sizes, int n_in,
                              void* d_out, int out_size)
{
    const int*   token_id    = (const int*)d_in[0];
    const int*   tag_id      = (const int*)d_in[1];
    const float* embed_table = (const float*)d_in[2];
    const float* conv_w      = (const float*)d_in[3];
    const float* conv_b      = (const float*)d_in[4];
    const float* out_w       = (const float*)d_in[5];
    const float* out_b       = (const float*)d_in[6];
    const float* start_trans = (const float*)d_in[7];
    const float* end_trans   = (const float*)d_in[8];
    const float* trans       = (const float*)d_in[9];

    cudaFuncSetAttribute(fused_kernel,
                         cudaFuncAttributeMaxDynamicSharedMemorySize, SMEM_TOTAL);

    prep_kernel<<<54, 256>>>(conv_w);
    fused_kernel<<<NCRF + (SS / CS) * BB, 256, SMEM_TOTAL>>>(
        token_id, tag_id, embed_table, conv_b, out_w, out_b,
        start_trans, end_trans, trans);
    final_kernel<<<1, 64>>>((float*)d_out);
}